// round 10
// baseline (speedup 1.0000x reference)
#include <cuda_runtime.h>
#include <cstdint>
#include <cstddef>

#define HID       512
#define NB        20
#define MT        32          // rows per CTA
#define NTHREADS  512
#define BK        16          // K rows per staged weight tile
#define KTILES    (HID / BK)  // 32
#define LN_EPS    1e-5f

typedef unsigned long long u64;

// ---------------- packed f32x2 helpers (FFMA2 path, 2x fp32 rate on sm_103a) ---
__device__ __forceinline__ u64 pk2(float x) {
    unsigned int u = __float_as_uint(x);
    u64 r;
    asm("mov.b64 %0, {%1, %1};" : "=l"(r) : "r"(u));
    return r;
}
__device__ __forceinline__ u64 fma2(u64 a, u64 b, u64 c) {
    u64 d;
    asm("fma.rn.f32x2 %0, %1, %2, %3;" : "=l"(d) : "l"(a), "l"(b), "l"(c));
    return d;
}
__device__ __forceinline__ float2 unpk(u64 v) {
    unsigned int lo, hi;
    asm("mov.b64 {%0, %1}, %2;" : "=r"(lo), "=r"(hi) : "l"(v));
    return make_float2(__uint_as_float(lo), __uint_as_float(hi));
}
__device__ __forceinline__ float silu_f(float z) {
    return z / (1.0f + __expf(-z));
}
__device__ __forceinline__ void cp16(unsigned int dst, const float* src) {
    asm volatile("cp.async.cg.shared.global [%0], [%1], 16;" :: "r"(dst), "l"(src) : "memory");
}

// ---------------- shared memory layout (float offsets) -------------------------
#define OFF_H    0                       // [32][512]       64 KB
#define OFF_U    16384                   // [32][512]       64 KB
#define OFF_W    32768                   // [2][16][512]    64 KB
#define OFF_MU   49152                   // [32]
#define OFF_RS   49184                   // [32]
#define OFF_RED  49216                   // [4][4][8][2] = 256
#define OFF_XS   49472                   // [64]
#define SMEM_FLOATS 49536                // 198144 bytes

// GEMM: acc[8][2] (f32x2 pairs over adjacent columns) += U[32,512] @ Wg[512,512]
// Thread map: rg = tid>>7 (rows rg+4i), cg = tid&127 (cols 4*cg..4*cg+3).
// A-operand loads are warp-broadcast; W loads are 512B-contiguous LDS.128.
__device__ __forceinline__ void gemm_tile(const float* __restrict__ Wg,
                                          const float* Us, float* Ws,
                                          u64 acc[8][2],
                                          int tid, int rg, int cg)
{
#pragma unroll
    for (int i = 0; i < 8; ++i) { acc[i][0] = 0ull; acc[i][1] = 0ull; }

    // staging chunk map: chunk c (of 2048 float4) -> row c>>7, col (c&127)*4
    const int ncol = (tid & 127) << 2;

    // stage tile 0 into buffer 0
    {
        float* Wb = Ws;
        const float* Gb = Wg;
#pragma unroll
        for (int j = 0; j < 4; ++j) {
            int c = tid + j * NTHREADS;
            int r = c >> 7;
            cp16((unsigned int)__cvta_generic_to_shared(Wb + r * HID + ncol),
                 Gb + r * HID + ncol);
        }
        asm volatile("cp.async.commit_group;" ::: "memory");
    }

    for (int t = 0; t < KTILES; ++t) {
        if (t + 1 < KTILES) {
            float* Wb = Ws + ((t + 1) & 1) * (BK * HID);
            const float* Gb = Wg + (size_t)(t + 1) * BK * HID;
#pragma unroll
            for (int j = 0; j < 4; ++j) {
                int c = tid + j * NTHREADS;
                int r = c >> 7;
                cp16((unsigned int)__cvta_generic_to_shared(Wb + r * HID + ncol),
                     Gb + r * HID + ncol);
            }
            asm volatile("cp.async.commit_group;" ::: "memory");
            asm volatile("cp.async.wait_group 1;" ::: "memory");
        } else {
            asm volatile("cp.async.wait_group 0;" ::: "memory");
        }
        __syncthreads();

        const float* Wb = Ws + (t & 1) * (BK * HID);
        const int k0 = t * BK;
#pragma unroll
        for (int kk = 0; kk < BK; kk += 4) {
            float4 a4[8];
#pragma unroll
            for (int i = 0; i < 8; ++i)
                a4[i] = *reinterpret_cast<const float4*>(Us + (rg + 4 * i) * HID + k0 + kk);
#pragma unroll
            for (int kq = 0; kq < 4; ++kq) {
                ulonglong2 wv = *reinterpret_cast<const ulonglong2*>(Wb + (kk + kq) * HID + 4 * cg);
#pragma unroll
                for (int i = 0; i < 8; ++i) {
                    float a = (kq == 0) ? a4[i].x : (kq == 1) ? a4[i].y
                            : (kq == 2) ? a4[i].z : a4[i].w;
                    u64 ap = pk2(a);
                    acc[i][0] = fma2(ap, wv.x, acc[i][0]);
                    acc[i][1] = fma2(ap, wv.y, acc[i][1]);
                }
            }
        }
        __syncthreads();
    }
}

__global__ void __launch_bounds__(NTHREADS, 1)
mlpres_kernel(const float* __restrict__ x,
              const float* __restrict__ in_w,
              const float* __restrict__ in_b,
              const float* __restrict__ ln1_g,
              const float* __restrict__ ln1_b,
              const float* __restrict__ fc1_w,
              const float* __restrict__ fc1_b,
              const float* __restrict__ ln2_g,
              const float* __restrict__ ln2_b,
              const float* __restrict__ fc2_w,
              const float* __restrict__ fc2_b,
              const float* __restrict__ out_ln_g,
              const float* __restrict__ out_ln_b,
              const float* __restrict__ out_w,
              const float* __restrict__ out_b,
              float* __restrict__ out)
{
    extern __shared__ float sm[];
    float* H   = sm + OFF_H;
    float* U   = sm + OFF_U;
    float* Ws  = sm + OFF_W;
    float* MU  = sm + OFF_MU;
    float* RS  = sm + OFF_RS;
    float* RED = sm + OFF_RED;
    float* XS  = sm + OFF_XS;

    const int tid  = threadIdx.x;
    const int rg   = tid >> 7;     // 0..3
    const int cg   = tid & 127;    // 0..127
    const int wid  = tid >> 5;     // 0..15
    const int lane = tid & 31;
    const int row0 = blockIdx.x * MT;

    // ---------------- prologue: H = silu(x @ in_w + in_b) ----------------
    if (tid < 2 * MT) XS[tid] = __ldg(x + (size_t)row0 * 2 + tid);
    __syncthreads();
#pragma unroll
    for (int c = tid; c < MT * 128; c += NTHREADS) {
        int m = c >> 7, p = (c & 127) << 2;
        float4 w0 = __ldg(reinterpret_cast<const float4*>(in_w + p));
        float4 w1 = __ldg(reinterpret_cast<const float4*>(in_w + HID + p));
        float4 bb = __ldg(reinterpret_cast<const float4*>(in_b + p));
        float x0 = XS[2 * m], x1 = XS[2 * m + 1];
        float4 h;
        h.x = silu_f(fmaf(x0, w0.x, fmaf(x1, w1.x, bb.x)));
        h.y = silu_f(fmaf(x0, w0.y, fmaf(x1, w1.y, bb.y)));
        h.z = silu_f(fmaf(x0, w0.z, fmaf(x1, w1.z, bb.z)));
        h.w = silu_f(fmaf(x0, w0.w, fmaf(x1, w1.w, bb.w)));
        *reinterpret_cast<float4*>(H + m * HID + p) = h;
    }

    u64 acc[8][2];

    // ---------------- 20 residual blocks ----------------
#pragma unroll 1
    for (int L = 0; L < NB; ++L) {
        __syncthreads();   // H updates from previous layer visible

        // --- stats of H (2 rows per warp, lanes strided, warp-reduce)
#pragma unroll
        for (int r = 0; r < 2; ++r) {
            int m = wid * 2 + r;
            float s = 0.f, q = 0.f;
#pragma unroll
            for (int j = 0; j < 16; ++j) {
                float v = H[m * HID + lane + 32 * j];
                s += v; q = fmaf(v, v, q);
            }
#pragma unroll
            for (int o = 16; o; o >>= 1) {
                s += __shfl_xor_sync(0xffffffffu, s, o);
                q += __shfl_xor_sync(0xffffffffu, q, o);
            }
            if (lane == 0) {
                float mu = s * (1.0f / HID);
                float var = q * (1.0f / HID) - mu * mu;
                MU[m] = mu;
                RS[m] = rsqrtf(var + LN_EPS);
            }
        }
        __syncthreads();

        // --- U = LN1(H)
        const float* g1 = ln1_g + (size_t)L * HID;
        const float* b1 = ln1_b + (size_t)L * HID;
#pragma unroll
        for (int c = tid; c < MT * 128; c += NTHREADS) {
            int m = c >> 7, p = (c & 127) << 2;
            float mu = MU[m], rs = RS[m];
            float4 hv = *reinterpret_cast<const float4*>(H + m * HID + p);
            float4 g = __ldg(reinterpret_cast<const float4*>(g1 + p));
            float4 b = __ldg(reinterpret_cast<const float4*>(b1 + p));
            float4 u;
            u.x = fmaf((hv.x - mu) * rs, g.x, b.x);
            u.y = fmaf((hv.y - mu) * rs, g.y, b.y);
            u.z = fmaf((hv.z - mu) * rs, g.z, b.z);
            u.w = fmaf((hv.w - mu) * rs, g.w, b.w);
            *reinterpret_cast<float4*>(U + m * HID + p) = u;
        }
        // (gemm's internal barrier after wait_group publishes U)

        // --- GEMM1: acc = U @ W1
        gemm_tile(fc1_w + (size_t)L * HID * HID, U, Ws, acc, tid, rg, cg);

        // --- t = silu(acc + fc1_b), partial stats in registers
        float tv[8][4];
        {
            float4 c1v = __ldg(reinterpret_cast<const float4*>(fc1_b + (size_t)L * HID + 4 * cg));
            float sr[8], qr[8];
#pragma unroll
            for (int i = 0; i < 8; ++i) {
                float2 p0 = unpk(acc[i][0]), p1 = unpk(acc[i][1]);
                tv[i][0] = silu_f(p0.x + c1v.x);
                tv[i][1] = silu_f(p0.y + c1v.y);
                tv[i][2] = silu_f(p1.x + c1v.z);
                tv[i][3] = silu_f(p1.y + c1v.w);
                sr[i] = tv[i][0] + tv[i][1] + tv[i][2] + tv[i][3];
                qr[i] = fmaf(tv[i][0], tv[i][0],
                        fmaf(tv[i][1], tv[i][1],
                        fmaf(tv[i][2], tv[i][2], tv[i][3] * tv[i][3])));
            }
#pragma unroll
            for (int i = 0; i < 8; ++i) {
#pragma unroll
                for (int o = 16; o; o >>= 1) {
                    sr[i] += __shfl_xor_sync(0xffffffffu, sr[i], o);
                    qr[i] += __shfl_xor_sync(0xffffffffu, qr[i], o);
                }
            }
            int w4 = (tid >> 5) & 3;
            if (lane == 0) {
#pragma unroll
                for (int i = 0; i < 8; ++i) {
                    RED[((rg * 4 + w4) * 8 + i) * 2 + 0] = sr[i];
                    RED[((rg * 4 + w4) * 8 + i) * 2 + 1] = qr[i];
                }
            }
        }
        __syncthreads();
        if (tid < MT) {
            int m = tid, mrg = m & 3, mi = m >> 2;
            float s = 0.f, q = 0.f;
#pragma unroll
            for (int w4 = 0; w4 < 4; ++w4) {
                s += RED[((mrg * 4 + w4) * 8 + mi) * 2 + 0];
                q += RED[((mrg * 4 + w4) * 8 + mi) * 2 + 1];
            }
            float mu = s * (1.0f / HID);
            float var = q * (1.0f / HID) - mu * mu;
            MU[m] = mu;
            RS[m] = rsqrtf(var + LN_EPS);
        }
        __syncthreads();

        // --- U = LN2(t) (registers -> SMEM)
        {
            float4 g = __ldg(reinterpret_cast<const float4*>(ln2_g + (size_t)L * HID + 4 * cg));
            float4 b = __ldg(reinterpret_cast<const float4*>(ln2_b + (size_t)L * HID + 4 * cg));
#pragma unroll
            for (int i = 0; i < 8; ++i) {
                int m = rg + 4 * i;
                float mu = MU[m], rs = RS[m];
                float4 u;
                u.x = fmaf((tv[i][0] - mu) * rs, g.x, b.x);
                u.y = fmaf((tv[i][1] - mu) * rs, g.y, b.y);
                u.z = fmaf((tv[i][2] - mu) * rs, g.z, b.z);
                u.w = fmaf((tv[i][3] - mu) * rs, g.w, b.w);
                *reinterpret_cast<float4*>(U + m * HID + 4 * cg) = u;
            }
        }

        // --- GEMM2: acc = U @ W2
        gemm_tile(fc2_w + (size_t)L * HID * HID, U, Ws, acc, tid, rg, cg);

        // --- H += acc + fc2_b (thread-exclusive RMW on its own elements)
        {
            float4 c2v = __ldg(reinterpret_cast<const float4*>(fc2_b + (size_t)L * HID + 4 * cg));
#pragma unroll
            for (int i = 0; i < 8; ++i) {
                int m = rg + 4 * i;
                float2 p0 = unpk(acc[i][0]), p1 = unpk(acc[i][1]);
                float4 hv = *reinterpret_cast<float4*>(H + m * HID + 4 * cg);
                hv.x += p0.x + c2v.x;
                hv.y += p0.y + c2v.y;
                hv.z += p1.x + c2v.z;
                hv.w += p1.y + c2v.w;
                *reinterpret_cast<float4*>(H + m * HID + 4 * cg) = hv;
            }
        }
    }

    __syncthreads();

    // ---------------- epilogue: out = silu(LN(H)) @ out_w + out_b ----------------
    const float ob = __ldg(out_b);
#pragma unroll
    for (int r = 0; r < 2; ++r) {
        int m = wid * 2 + r;
        float s = 0.f, q = 0.f;
#pragma unroll
        for (int j = 0; j < 16; ++j) {
            float v = H[m * HID + lane + 32 * j];
            s += v; q = fmaf(v, v, q);
        }
#pragma unroll
        for (int o = 16; o; o >>= 1) {
            s += __shfl_xor_sync(0xffffffffu, s, o);
            q += __shfl_xor_sync(0xffffffffu, q, o);
        }
        float mu = s * (1.0f / HID);
        float rs = rsqrtf(q * (1.0f / HID) - mu * mu + LN_EPS);
        float d = 0.f;
#pragma unroll
        for (int j = 0; j < 16; ++j) {
            int n = lane + 32 * j;
            float v = H[m * HID + n];
            v = fmaf((v - mu) * rs, __ldg(out_ln_g + n), __ldg(out_ln_b + n));
            d = fmaf(silu_f(v), __ldg(out_w + n), d);
        }
#pragma unroll
        for (int o = 16; o; o >>= 1)
            d += __shfl_xor_sync(0xffffffffu, d, o);
        if (lane == 0)
            out[row0 + m] = d + ob;
    }
}

extern "C" void kernel_launch(void* const* d_in, const int* in_sizes, int n_in,
                              void* d_out, int out_size)
{
    const float* x        = (const float*)d_in[0];
    const float* in_w     = (const float*)d_in[1];
    const float* in_b     = (const float*)d_in[2];
    const float* ln1_g    = (const float*)d_in[3];
    const float* ln1_b    = (const float*)d_in[4];
    const float* fc1_w    = (const float*)d_in[5];
    const float* fc1_b    = (const float*)d_in[6];
    const float* ln2_g    = (const float*)d_in[7];
    const float* ln2_b    = (const float*)d_in[8];
    const float* fc2_w    = (const float*)d_in[9];
    const float* fc2_b    = (const float*)d_in[10];
    const float* out_ln_g = (const float*)d_in[11];
    const float* out_ln_b = (const float*)d_in[12];
    const float* out_w    = (const float*)d_in[13];
    const float* out_b    = (const float*)d_in[14];
    float* out = (float*)d_out;

    const int nrows = in_sizes[0] / 2;      // 65536
    const int grid  = nrows / MT;           // 2048
    const size_t smem = SMEM_FLOATS * sizeof(float);  // 198144 B

    cudaFuncSetAttribute(mlpres_kernel,
                         cudaFuncAttributeMaxDynamicSharedMemorySize, (int)smem);

    mlpres_kernel<<<grid, NTHREADS, smem>>>(
        x, in_w, in_b, ln1_g, ln1_b, fc1_w, fc1_b,
        ln2_g, ln2_b, fc2_w, fc2_b, out_ln_g, out_ln_b, out_w, out_b, out);
}

// round 11
// speedup vs baseline: 1.6441x; 1.6441x over previous
#include <cuda_runtime.h>
#include <cstdint>
#include <cstddef>

#define HID       512
#define NB        20
#define MT        32          // rows per CTA
#define NTHREADS  512
#define BK        16          // K rows per staged weight tile
#define KTILES    (HID / BK)  // 32
#define LN_EPS    1e-5f

typedef unsigned long long u64;

// ---------------- packed f32x2 helpers (FFMA2 path, 2x fp32 rate on sm_103a) ---
__device__ __forceinline__ u64 pk2(float x) {
    unsigned int u = __float_as_uint(x);
    u64 r;
    asm("mov.b64 %0, {%1, %1};" : "=l"(r) : "r"(u));
    return r;
}
__device__ __forceinline__ u64 fma2(u64 a, u64 b, u64 c) {
    u64 d;
    asm("fma.rn.f32x2 %0, %1, %2, %3;" : "=l"(d) : "l"(a), "l"(b), "l"(c));
    return d;
}
__device__ __forceinline__ float2 unpk(u64 v) {
    unsigned int lo, hi;
    asm("mov.b64 {%0, %1}, %2;" : "=r"(lo), "=r"(hi) : "l"(v));
    return make_float2(__uint_as_float(lo), __uint_as_float(hi));
}
__device__ __forceinline__ float silu_f(float z) {
    return z / (1.0f + __expf(-z));
}
__device__ __forceinline__ void cp16(unsigned int dst, const float* src) {
    asm volatile("cp.async.cg.shared.global [%0], [%1], 16;" :: "r"(dst), "l"(src) : "memory");
}

// ---------------- shared memory layout (float offsets) -------------------------
#define OFF_H    0                       // [32][512]       64 KB
#define OFF_U    16384                   // [32][512]       64 KB
#define OFF_W    32768                   // [2][16][512]    64 KB
#define OFF_MU   49152                   // [32]
#define OFF_RS   49184                   // [32]
#define OFF_RED  49216                   // [4][4][8][2] = 256
#define OFF_XS   49472                   // [64]
#define SMEM_FLOATS 49536                // 198144 bytes

// GEMM: acc[8][2] (f32x2 pairs over adjacent columns) += U[32,512] @ Wg[512,512]
// Thread map: rg = tid>>7 (rows rg+4i), cg = tid&127 (cols 4*cg..4*cg+3).
// A-operand loads are warp-broadcast; W loads are 512B-contiguous LDS.128.
__device__ __forceinline__ void gemm_tile(const float* __restrict__ Wg,
                                          const float* Us, float* Ws,
                                          u64 acc[8][2],
                                          int tid, int rg, int cg)
{
#pragma unroll
    for (int i = 0; i < 8; ++i) { acc[i][0] = 0ull; acc[i][1] = 0ull; }

    // staging chunk map: chunk c (of 2048 float4) -> row c>>7, col (c&127)*4
    const int ncol = (tid & 127) << 2;

    // stage tile 0 into buffer 0
    {
        float* Wb = Ws;
        const float* Gb = Wg;
#pragma unroll
        for (int j = 0; j < 4; ++j) {
            int c = tid + j * NTHREADS;
            int r = c >> 7;
            cp16((unsigned int)__cvta_generic_to_shared(Wb + r * HID + ncol),
                 Gb + r * HID + ncol);
        }
        asm volatile("cp.async.commit_group;" ::: "memory");
    }

    for (int t = 0; t < KTILES; ++t) {
        if (t + 1 < KTILES) {
            float* Wb = Ws + ((t + 1) & 1) * (BK * HID);
            const float* Gb = Wg + (size_t)(t + 1) * BK * HID;
#pragma unroll
            for (int j = 0; j < 4; ++j) {
                int c = tid + j * NTHREADS;
                int r = c >> 7;
                cp16((unsigned int)__cvta_generic_to_shared(Wb + r * HID + ncol),
                     Gb + r * HID + ncol);
            }
            asm volatile("cp.async.commit_group;" ::: "memory");
            asm volatile("cp.async.wait_group 1;" ::: "memory");
        } else {
            asm volatile("cp.async.wait_group 0;" ::: "memory");
        }
        __syncthreads();

        const float* Wb = Ws + (t & 1) * (BK * HID);
        const int k0 = t * BK;
#pragma unroll
        for (int kk = 0; kk < BK; kk += 4) {
            float4 a4[8];
#pragma unroll
            for (int i = 0; i < 8; ++i)
                a4[i] = *reinterpret_cast<const float4*>(Us + (rg + 4 * i) * HID + k0 + kk);
#pragma unroll
            for (int kq = 0; kq < 4; ++kq) {
                ulonglong2 wv = *reinterpret_cast<const ulonglong2*>(Wb + (kk + kq) * HID + 4 * cg);
#pragma unroll
                for (int i = 0; i < 8; ++i) {
                    float a = (kq == 0) ? a4[i].x : (kq == 1) ? a4[i].y
                            : (kq == 2) ? a4[i].z : a4[i].w;
                    u64 ap = pk2(a);
                    acc[i][0] = fma2(ap, wv.x, acc[i][0]);
                    acc[i][1] = fma2(ap, wv.y, acc[i][1]);
                }
            }
        }
        __syncthreads();
    }
}

__global__ void __launch_bounds__(NTHREADS, 1)
mlpres_kernel(const float* __restrict__ x,
              const float* __restrict__ in_w,
              const float* __restrict__ in_b,
              const float* __restrict__ ln1_g,
              const float* __restrict__ ln1_b,
              const float* __restrict__ fc1_w,
              const float* __restrict__ fc1_b,
              const float* __restrict__ ln2_g,
              const float* __restrict__ ln2_b,
              const float* __restrict__ fc2_w,
              const float* __restrict__ fc2_b,
              const float* __restrict__ out_ln_g,
              const float* __restrict__ out_ln_b,
              const float* __restrict__ out_w,
              const float* __restrict__ out_b,
              float* __restrict__ out)
{
    extern __shared__ float sm[];
    float* H   = sm + OFF_H;
    float* U   = sm + OFF_U;
    float* Ws  = sm + OFF_W;
    float* MU  = sm + OFF_MU;
    float* RS  = sm + OFF_RS;
    float* RED = sm + OFF_RED;
    float* XS  = sm + OFF_XS;

    const int tid  = threadIdx.x;
    const int rg   = tid >> 7;     // 0..3
    const int cg   = tid & 127;    // 0..127
    const int wid  = tid >> 5;     // 0..15
    const int lane = tid & 31;
    const int row0 = blockIdx.x * MT;

    // ---------------- prologue: H = silu(x @ in_w + in_b) ----------------
    if (tid < 2 * MT) XS[tid] = __ldg(x + (size_t)row0 * 2 + tid);
    __syncthreads();
#pragma unroll
    for (int c = tid; c < MT * 128; c += NTHREADS) {
        int m = c >> 7, p = (c & 127) << 2;
        float4 w0 = __ldg(reinterpret_cast<const float4*>(in_w + p));
        float4 w1 = __ldg(reinterpret_cast<const float4*>(in_w + HID + p));
        float4 bb = __ldg(reinterpret_cast<const float4*>(in_b + p));
        float x0 = XS[2 * m], x1 = XS[2 * m + 1];
        float4 h;
        h.x = silu_f(fmaf(x0, w0.x, fmaf(x1, w1.x, bb.x)));
        h.y = silu_f(fmaf(x0, w0.y, fmaf(x1, w1.y, bb.y)));
        h.z = silu_f(fmaf(x0, w0.z, fmaf(x1, w1.z, bb.z)));
        h.w = silu_f(fmaf(x0, w0.w, fmaf(x1, w1.w, bb.w)));
        *reinterpret_cast<float4*>(H + m * HID + p) = h;
    }

    u64 acc[8][2];

    // ---------------- 20 residual blocks ----------------
#pragma unroll 1
    for (int L = 0; L < NB; ++L) {
        __syncthreads();   // H updates from previous layer visible

        // --- stats of H (2 rows per warp, lanes strided, warp-reduce)
#pragma unroll
        for (int r = 0; r < 2; ++r) {
            int m = wid * 2 + r;
            float s = 0.f, q = 0.f;
#pragma unroll
            for (int j = 0; j < 16; ++j) {
                float v = H[m * HID + lane + 32 * j];
                s += v; q = fmaf(v, v, q);
            }
#pragma unroll
            for (int o = 16; o; o >>= 1) {
                s += __shfl_xor_sync(0xffffffffu, s, o);
                q += __shfl_xor_sync(0xffffffffu, q, o);
            }
            if (lane == 0) {
                float mu = s * (1.0f / HID);
                float var = q * (1.0f / HID) - mu * mu;
                MU[m] = mu;
                RS[m] = rsqrtf(var + LN_EPS);
            }
        }
        __syncthreads();

        // --- U = LN1(H)
        const float* g1 = ln1_g + (size_t)L * HID;
        const float* b1 = ln1_b + (size_t)L * HID;
#pragma unroll
        for (int c = tid; c < MT * 128; c += NTHREADS) {
            int m = c >> 7, p = (c & 127) << 2;
            float mu = MU[m], rs = RS[m];
            float4 hv = *reinterpret_cast<const float4*>(H + m * HID + p);
            float4 g = __ldg(reinterpret_cast<const float4*>(g1 + p));
            float4 b = __ldg(reinterpret_cast<const float4*>(b1 + p));
            float4 u;
            u.x = fmaf((hv.x - mu) * rs, g.x, b.x);
            u.y = fmaf((hv.y - mu) * rs, g.y, b.y);
            u.z = fmaf((hv.z - mu) * rs, g.z, b.z);
            u.w = fmaf((hv.w - mu) * rs, g.w, b.w);
            *reinterpret_cast<float4*>(U + m * HID + p) = u;
        }
        // (gemm's internal barrier after wait_group publishes U)

        // --- GEMM1: acc = U @ W1
        gemm_tile(fc1_w + (size_t)L * HID * HID, U, Ws, acc, tid, rg, cg);

        // --- t = silu(acc + fc1_b), partial stats in registers
        float tv[8][4];
        {
            float4 c1v = __ldg(reinterpret_cast<const float4*>(fc1_b + (size_t)L * HID + 4 * cg));
            float sr[8], qr[8];
#pragma unroll
            for (int i = 0; i < 8; ++i) {
                float2 p0 = unpk(acc[i][0]), p1 = unpk(acc[i][1]);
                tv[i][0] = silu_f(p0.x + c1v.x);
                tv[i][1] = silu_f(p0.y + c1v.y);
                tv[i][2] = silu_f(p1.x + c1v.z);
                tv[i][3] = silu_f(p1.y + c1v.w);
                sr[i] = tv[i][0] + tv[i][1] + tv[i][2] + tv[i][3];
                qr[i] = fmaf(tv[i][0], tv[i][0],
                        fmaf(tv[i][1], tv[i][1],
                        fmaf(tv[i][2], tv[i][2], tv[i][3] * tv[i][3])));
            }
#pragma unroll
            for (int i = 0; i < 8; ++i) {
#pragma unroll
                for (int o = 16; o; o >>= 1) {
                    sr[i] += __shfl_xor_sync(0xffffffffu, sr[i], o);
                    qr[i] += __shfl_xor_sync(0xffffffffu, qr[i], o);
                }
            }
            int w4 = (tid >> 5) & 3;
            if (lane == 0) {
#pragma unroll
                for (int i = 0; i < 8; ++i) {
                    RED[((rg * 4 + w4) * 8 + i) * 2 + 0] = sr[i];
                    RED[((rg * 4 + w4) * 8 + i) * 2 + 1] = qr[i];
                }
            }
        }
        __syncthreads();
        if (tid < MT) {
            int m = tid, mrg = m & 3, mi = m >> 2;
            float s = 0.f, q = 0.f;
#pragma unroll
            for (int w4 = 0; w4 < 4; ++w4) {
                s += RED[((mrg * 4 + w4) * 8 + mi) * 2 + 0];
                q += RED[((mrg * 4 + w4) * 8 + mi) * 2 + 1];
            }
            float mu = s * (1.0f / HID);
            float var = q * (1.0f / HID) - mu * mu;
            MU[m] = mu;
            RS[m] = rsqrtf(var + LN_EPS);
        }
        __syncthreads();

        // --- U = LN2(t) (registers -> SMEM)
        {
            float4 g = __ldg(reinterpret_cast<const float4*>(ln2_g + (size_t)L * HID + 4 * cg));
            float4 b = __ldg(reinterpret_cast<const float4*>(ln2_b + (size_t)L * HID + 4 * cg));
#pragma unroll
            for (int i = 0; i < 8; ++i) {
                int m = rg + 4 * i;
                float mu = MU[m], rs = RS[m];
                float4 u;
                u.x = fmaf((tv[i][0] - mu) * rs, g.x, b.x);
                u.y = fmaf((tv[i][1] - mu) * rs, g.y, b.y);
                u.z = fmaf((tv[i][2] - mu) * rs, g.z, b.z);
                u.w = fmaf((tv[i][3] - mu) * rs, g.w, b.w);
                *reinterpret_cast<float4*>(U + m * HID + 4 * cg) = u;
            }
        }

        // --- GEMM2: acc = U @ W2
        gemm_tile(fc2_w + (size_t)L * HID * HID, U, Ws, acc, tid, rg, cg);

        // --- H += acc + fc2_b (thread-exclusive RMW on its own elements)
        {
            float4 c2v = __ldg(reinterpret_cast<const float4*>(fc2_b + (size_t)L * HID + 4 * cg));
#pragma unroll
            for (int i = 0; i < 8; ++i) {
                int m = rg + 4 * i;
                float2 p0 = unpk(acc[i][0]), p1 = unpk(acc[i][1]);
                float4 hv = *reinterpret_cast<float4*>(H + m * HID + 4 * cg);
                hv.x += p0.x + c2v.x;
                hv.y += p0.y + c2v.y;
                hv.z += p1.x + c2v.z;
                hv.w += p1.y + c2v.w;
                *reinterpret_cast<float4*>(H + m * HID + 4 * cg) = hv;
            }
        }
    }

    __syncthreads();

    // ---------------- epilogue: out = silu(LN(H)) @ out_w + out_b ----------------
    const float ob = __ldg(out_b);
#pragma unroll
    for (int r = 0; r < 2; ++r) {
        int m = wid * 2 + r;
        float s = 0.f, q = 0.f;
#pragma unroll
        for (int j = 0; j < 16; ++j) {
            float v = H[m * HID + lane + 32 * j];
            s += v; q = fmaf(v, v, q);
        }
#pragma unroll
        for (int o = 16; o; o >>= 1) {
            s += __shfl_xor_sync(0xffffffffu, s, o);
            q += __shfl_xor_sync(0xffffffffu, q, o);
        }
        float mu = s * (1.0f / HID);
        float rs = rsqrtf(q * (1.0f / HID) - mu * mu + LN_EPS);
        float d = 0.f;
#pragma unroll
        for (int j = 0; j < 16; ++j) {
            int n = lane + 32 * j;
            float v = H[m * HID + n];
            v = fmaf((v - mu) * rs, __ldg(out_ln_g + n), __ldg(out_ln_b + n));
            d = fmaf(silu_f(v), __ldg(out_w + n), d);
        }
#pragma unroll
        for (int o = 16; o; o >>= 1)
            d += __shfl_xor_sync(0xffffffffu, d, o);
        if (lane == 0)
            out[row0 + m] = d + ob;
    }
}

extern "C" void kernel_launch(void* const* d_in, const int* in_sizes, int n_in,
                              void* d_out, int out_size)
{
    const float* x        = (const float*)d_in[0];
    const float* in_w     = (const float*)d_in[1];
    const float* in_b     = (const float*)d_in[2];
    const float* ln1_g    = (const float*)d_in[3];
    const float* ln1_b    = (const float*)d_in[4];
    const float* fc1_w    = (const float*)d_in[5];
    const float* fc1_b    = (const float*)d_in[6];
    const float* ln2_g    = (const float*)d_in[7];
    const float* ln2_b    = (const float*)d_in[8];
    const float* fc2_w    = (const float*)d_in[9];
    const float* fc2_b    = (const float*)d_in[10];
    const float* out_ln_g = (const float*)d_in[11];
    const float* out_ln_b = (const float*)d_in[12];
    const float* out_w    = (const float*)d_in[13];
    const float* out_b    = (const float*)d_in[14];
    float* out = (float*)d_out;

    const int nrows = in_sizes[0] / 2;      // 65536
    const int grid  = nrows / MT;           // 2048
    const size_t smem = SMEM_FLOATS * sizeof(float);  // 198144 B

    cudaFuncSetAttribute(mlpres_kernel,
                         cudaFuncAttributeMaxDynamicSharedMemorySize, (int)smem);

    mlpres_kernel<<<grid, NTHREADS, smem>>>(
        x, in_w, in_b, ln1_g, ln1_b, fc1_w, fc1_b,
        ln2_g, ln2_b, fc2_w, fc2_b, out_ln_g, out_ln_b, out_w, out_b, out);
}